// round 8
// baseline (speedup 1.0000x reference)
#include <cuda_runtime.h>
#include <math.h>

// Problem dims
#define BB 4
#define CC 64
#define TT 8
#define XX 96
#define YY 96
#define SS 9216            // XX*YY
#define VOL 18874368       // BB*CC*TT*SS
#define NTOK 36864         // BB*SS  (attention batch)
#define CHN 294912         // BB*TT*SS (elements per channel for BN)

// Scratch (device globals: the sanctioned no-alloc workaround)
__device__ float g_xc[VOL];      // conv0 output (pre-BN)
__device__ float g_q[VOL];       // [t][c][n]
__device__ float g_k[VOL];
__device__ float g_v[VOL];
__device__ float g_s[VOL];       // x + attn_out (pre-BN1)
__device__ float g_part[2 * 64 * 72];
__device__ float g_bn0[128];     // a[64], shift[64]
__device__ float g_bn1[128];
__device__ float g_m[2048];      // [b][c][t]
__device__ float g_w5[800];      // [b][t][25]

__device__ __forceinline__ float leaky(float v) { return v >= 0.f ? v : 0.01f * v; }

// ---------------------------------------------------------------------------
// K1: conv0  (3x3 over X,Y; pad 1; 64->64 channels) -> g_xc
// Block: one (b,t,x) row. 256 thr = 64 c_out x 4 y-groups of 24.
// Weights live in registers; input rows broadcast from smem.
// ---------------------------------------------------------------------------
__global__ __launch_bounds__(256) void k_conv0(const float* __restrict__ h,
                                               const float* __restrict__ w,
                                               const float* __restrict__ bias) {
    __shared__ __align__(16) float in_s[3][100];
    __shared__ float w_s[576];
    int bt = blockIdx.y;
    int b = bt >> 3, t = bt & 7;
    int x = blockIdx.x;
    int co = threadIdx.x & 63;
    int yg = threadIdx.x >> 6;
    int ybase = yg * 24;

    float acc[24];
#pragma unroll
    for (int i = 0; i < 24; i++) acc[i] = 0.f;

    const float* hp = h + ((long)(b * 64) * 8 + t) * 9216;  // + ci*73728

    for (int ci = 0; ci < 64; ci++) {
        __syncthreads();
        for (int i = threadIdx.x; i < 294; i += 256) {
            int r = i / 98, yy = i - r * 98;
            int gx = x + r - 1, gy = yy - 1;
            float v = 0.f;
            if ((unsigned)gx < 96u && (unsigned)gy < 96u)
                v = hp[ci * 73728 + gx * 96 + gy];
            in_s[r][yy] = v;
        }
        for (int i = threadIdx.x; i < 576; i += 256) {
            int o = i / 9, k = i - o * 9;
            w_s[i] = w[(o * 64 + ci) * 9 + k];
        }
        __syncthreads();

        float wr[9];
#pragma unroll
        for (int k = 0; k < 9; k++) wr[k] = w_s[co * 9 + k];

#pragma unroll
        for (int r = 0; r < 3; r++) {
            float v[26];
#pragma unroll
            for (int j = 0; j < 26; j++) v[j] = in_s[r][ybase + j];
#pragma unroll
            for (int y = 0; y < 24; y++)
                acc[y] = fmaf(v[y], wr[r * 3],
                          fmaf(v[y + 1], wr[r * 3 + 1],
                           fmaf(v[y + 2], wr[r * 3 + 2], acc[y])));
        }
    }
    float bb = bias[co];
    float* op = g_xc + ((b * 64 + co) * 8 + t) * 9216 + x * 96 + ybase;
#pragma unroll
    for (int y = 0; y < 24; y++) op[y] = acc[y] + bb;
}

// ---------------------------------------------------------------------------
// K2: per-channel sum / sumsq partials (deterministic two-stage reduction)
// which==0: g_xc ; which==1: g_s
// ---------------------------------------------------------------------------
__global__ __launch_bounds__(256) void k_stats(int which) {
    const float* src = which ? g_s : g_xc;
    int c = blockIdx.x;
    int chunk = blockIdx.y;
    float s = 0.f, q = 0.f;
    for (int i = threadIdx.x; i < 4096; i += 256) {
        int j = chunk * 4096 + i;           // j in [0, 294912)
        int b = j / 73728;
        int r = j - b * 73728;
        float v = src[(b * 64 + c) * 73728 + r];
        s += v; q += v * v;
    }
    __shared__ float rs[256], rq[256];
    rs[threadIdx.x] = s; rq[threadIdx.x] = q;
    __syncthreads();
    for (int st = 128; st > 0; st >>= 1) {
        if (threadIdx.x < st) { rs[threadIdx.x] += rs[threadIdx.x + st];
                                rq[threadIdx.x] += rq[threadIdx.x + st]; }
        __syncthreads();
    }
    if (threadIdx.x == 0) {
        g_part[c * 72 + chunk] = rs[0];
        g_part[4608 + c * 72 + chunk] = rq[0];
    }
}

__global__ void k_finalize(int which, const float* __restrict__ gamma,
                           const float* __restrict__ beta) {
    int c = threadIdx.x;  // 64 threads
    float s = 0.f, q = 0.f;
    for (int i = 0; i < 72; i++) { s += g_part[c * 72 + i]; q += g_part[4608 + c * 72 + i]; }
    float mean = s * (1.f / 294912.f);
    float var = q * (1.f / 294912.f) - mean * mean;
    float a = gamma[c] * rsqrtf(var + 1e-5f);
    float* dst = which ? g_bn1 : g_bn0;
    dst[c] = a;
    dst[64 + c] = beta[c] - mean * a;
}

// ---------------------------------------------------------------------------
// K3: QKV projection. Per (b,t): Out[192][9216] = W[192][64] @ leaky(bn0(xc)).
// Block = 128 positions; thread tile 8 outs x 4 positions; q scaled by 1/sqrt(8).
// q/k/v written in layout [t][c][n], n = b*9216 + x*96 + y.
// ---------------------------------------------------------------------------
__global__ __launch_bounds__(256) void k_qkv(const float* __restrict__ W,
                                             const float* __restrict__ Wb) {
    extern __shared__ __align__(16) float sm[];
    float* in_s = sm;             // 64*128
    float* w_s = sm + 8192;       // 64*196 (padded, transposed: w_s[c][out])
    int bt = blockIdx.y;
    int b = bt >> 3, t = bt & 7;
    int s0 = blockIdx.x * 128;

    for (int i = threadIdx.x; i < 12288; i += 256) {
        int o = i >> 6, c = i & 63;
        w_s[c * 196 + o] = W[i];
    }
    for (int i = threadIdx.x; i < 8192; i += 256) {
        int c = i >> 7, p = i & 127;
        float raw = g_xc[((b * 64 + c) * 8 + t) * 9216 + s0 + p];
        in_s[i] = leaky(g_bn0[c] * raw + g_bn0[64 + c]);
    }
    __syncthreads();

    int pg = threadIdx.x & 31;
    int og = threadIdx.x >> 5;
    for (int p = 0; p < 3; p++) {
        float acc[8][4];
#pragma unroll
        for (int i = 0; i < 8; i++)
#pragma unroll
            for (int j = 0; j < 4; j++) acc[i][j] = 0.f;

        for (int c = 0; c < 64; c++) {
            float4 xin = *(const float4*)&in_s[c * 128 + pg * 4];
            float4 wa  = *(const float4*)&w_s[c * 196 + p * 64 + og * 8];
            float4 wb4 = *(const float4*)&w_s[c * 196 + p * 64 + og * 8 + 4];
            float wv[8] = {wa.x, wa.y, wa.z, wa.w, wb4.x, wb4.y, wb4.z, wb4.w};
            float xv[4] = {xin.x, xin.y, xin.z, xin.w};
#pragma unroll
            for (int i = 0; i < 8; i++)
#pragma unroll
                for (int j = 0; j < 4; j++)
                    acc[i][j] = fmaf(wv[i], xv[j], acc[i][j]);
        }
        float* dst = (p == 0) ? g_q : (p == 1 ? g_k : g_v);
        float scale = (p == 0) ? 0.35355339059327373f : 1.f;
#pragma unroll
        for (int i = 0; i < 8; i++) {
            int o = og * 8 + i;
            float bv = Wb[p * 64 + o];
            float4 r;
            r.x = (acc[i][0] + bv) * scale;
            r.y = (acc[i][1] + bv) * scale;
            r.z = (acc[i][2] + bv) * scale;
            r.w = (acc[i][3] + bv) * scale;
            *(float4*)&dst[(t * 64 + o) * 36864 + b * 9216 + s0 + pg * 4] = r;
        }
    }
}

// ---------------------------------------------------------------------------
// K4: attention core + out-proj + residual -> g_s
// Block handles 16 tokens. smem tiles [t*64+c][17] (pad) for q/k/v.
// Phase B: thread = (token, head, qt-half). Phase C: out-proj GEMM + x residual.
// ---------------------------------------------------------------------------
__global__ __launch_bounds__(256) void k_attn(const float* __restrict__ Wo,
                                              const float* __restrict__ bo) {
    extern __shared__ __align__(16) float sm[];
    float* q_s  = sm;              // 512*17 = 8704
    float* k_s  = sm + 8704;
    float* v_s  = sm + 17408;
    float* o_s  = sm + 26112;      // 16*516 = 8256
    float* wo_s = sm + 34368;      // 4096
    float* ab_s = sm + 38464;      // 128
    float* bo_s = sm + 38592;      // 64

    int n0 = blockIdx.x * 16;
    int b = n0 / 9216;
    int s0 = n0 - b * 9216;

    for (int i = threadIdx.x; i < 8192; i += 256) {
        int tc = i >> 4, nl = i & 15;
        int ga = tc * 36864 + n0 + nl;
        q_s[tc * 17 + nl] = g_q[ga];
        k_s[tc * 17 + nl] = g_k[ga];
        v_s[tc * 17 + nl] = g_v[ga];
    }
    for (int i = threadIdx.x; i < 4096; i += 256) wo_s[i] = Wo[i];
    if (threadIdx.x < 128) ab_s[threadIdx.x] = g_bn0[threadIdx.x];
    else if (threadIdx.x < 192) bo_s[threadIdx.x - 128] = bo[threadIdx.x - 128];
    __syncthreads();

    // Phase B: per-(token, head) attention over T=8
    {
        int u = threadIdx.x >> 7;
        int rem = threadIdx.x & 127;
        int nl = rem & 15;
        int hh = rem >> 4;
#pragma unroll
        for (int qi = 0; qi < 4; qi++) {
            int qt = u * 4 + qi;
            float qr[8];
#pragma unroll
            for (int d = 0; d < 8; d++) qr[d] = q_s[(qt * 64 + hh * 8 + d) * 17 + nl];
            float sc[8];
#pragma unroll
            for (int kt = 0; kt < 8; kt++) {
                float s = 0.f;
#pragma unroll
                for (int d = 0; d < 8; d++)
                    s = fmaf(qr[d], k_s[(kt * 64 + hh * 8 + d) * 17 + nl], s);
                sc[kt] = s;
            }
            float mx = sc[0];
#pragma unroll
            for (int kt = 1; kt < 8; kt++) mx = fmaxf(mx, sc[kt]);
            float sum = 0.f;
#pragma unroll
            for (int kt = 0; kt < 8; kt++) { sc[kt] = __expf(sc[kt] - mx); sum += sc[kt]; }
            float inv = 1.f / sum;
#pragma unroll
            for (int d = 0; d < 8; d++) {
                float o = 0.f;
#pragma unroll
                for (int kt = 0; kt < 8; kt++)
                    o = fmaf(sc[kt], v_s[(kt * 64 + hh * 8 + d) * 17 + nl], o);
                o_s[nl * 516 + qt * 64 + hh * 8 + d] = o * inv;
            }
        }
    }
    __syncthreads();

    // Phase C: out-proj + residual (x = leaky(bn0(xc))) -> g_s
    for (int idx = threadIdx.x; idx < 8192; idx += 256) {
        int nl = idx & 15;
        int co = (idx >> 4) & 63;
        int t = idx >> 10;
        float acc = bo_s[co];
        const float* orow = &o_s[nl * 516 + t * 64];
        const float* wrow = &wo_s[co * 64];
#pragma unroll
        for (int c = 0; c < 64; c += 4) {
            float4 ov = *(const float4*)&orow[c];
            float4 wv = *(const float4*)&wrow[c];
            acc = fmaf(ov.x, wv.x, acc);
            acc = fmaf(ov.y, wv.y, acc);
            acc = fmaf(ov.z, wv.z, acc);
            acc = fmaf(ov.w, wv.w, acc);
        }
        int ga = ((b * 64 + co) * 8 + t) * 9216 + s0 + nl;
        float x = leaky(ab_s[co] * g_xc[ga] + ab_s[64 + co]);
        g_s[ga] = x + acc;
    }
}

// ---------------------------------------------------------------------------
// K6: m[b,c,t] = spatial mean of leaky(bn1(g_s))
// ---------------------------------------------------------------------------
__global__ __launch_bounds__(256) void k_mred() {
    int bct = blockIdx.x;            // (b*64+c)*8+t
    int c = (bct >> 3) & 63;
    float a = g_bn1[c], sh = g_bn1[64 + c];
    const float* p = g_s + bct * 9216;
    float s = 0.f;
    for (int i = threadIdx.x; i < 9216; i += 256) s += leaky(a * p[i] + sh);
    __shared__ float rs[256];
    rs[threadIdx.x] = s;
    __syncthreads();
    for (int st = 128; st > 0; st >>= 1) {
        if (threadIdx.x < st) rs[threadIdx.x] += rs[threadIdx.x + st];
        __syncthreads();
    }
    if (threadIdx.x == 0) g_m[bct] = rs[0] * (1.f / 9216.f);
}

// ---------------------------------------------------------------------------
// K7: per-(b,t) 5x5 kernels: w5[b,t,o] = conv1_w[o,:]·m[b,:,t] + conv1_b[o]
// ---------------------------------------------------------------------------
__global__ void k_kern(const float* __restrict__ w1, const float* __restrict__ b1) {
    for (int i = threadIdx.x; i < 800; i += 256) {
        int b = i / 200;
        int rem = i - b * 200;
        int o = rem / 8;
        int t = rem - o * 8;
        float s = b1[o];
        for (int c = 0; c < 64; c++)
            s = fmaf(w1[o * 64 + c], g_m[(b * 64 + c) * 8 + t], s);
        g_w5[(b * 8 + t) * 25 + o] = s;
    }
}

// ---------------------------------------------------------------------------
// K8: dynamic depthwise 5x5 conv on h with per-(b,t) kernels -> d_out
// ---------------------------------------------------------------------------
__global__ __launch_bounds__(256) void k_dyn(const float* __restrict__ h,
                                             float* __restrict__ out) {
    __shared__ __align__(16) float in_s[12][100];
    __shared__ float w_s[25];
    int plane = blockIdx.y;          // (b*64+c)*8+t
    int b = plane >> 9;
    int t = plane & 7;
    int bt = b * 8 + t;
    int x0 = blockIdx.x * 8;

    if (threadIdx.x < 25) w_s[threadIdx.x] = g_w5[bt * 25 + threadIdx.x];
    for (int i = threadIdx.x; i < 1200; i += 256) {
        int r = i / 100, cc = i - r * 100;
        int gx = x0 + r - 2, gy = cc - 2;
        float v = 0.f;
        if ((unsigned)gx < 96u && (unsigned)gy < 96u)
            v = h[plane * 9216 + gx * 96 + gy];
        in_s[r][cc] = v;
    }
    __syncthreads();
    for (int o = threadIdx.x; o < 768; o += 256) {
        int xr = o / 96, y = o - xr * 96;
        float acc = 0.f;
#pragma unroll
        for (int di = 0; di < 5; di++)
#pragma unroll
            for (int dj = 0; dj < 5; dj++)
                acc = fmaf(in_s[xr + di][y + dj], w_s[di * 5 + dj], acc);
        out[plane * 9216 + (x0 + xr) * 96 + y] = acc;
    }
}

// ---------------------------------------------------------------------------
extern "C" void kernel_launch(void* const* d_in, const int* in_sizes, int n_in,
                              void* d_out, int out_size) {
    const float* h       = (const float*)d_in[0];
    const float* conv0_w = (const float*)d_in[1];
    const float* conv0_b = (const float*)d_in[2];
    const float* bn0_g   = (const float*)d_in[3];
    const float* bn0_b   = (const float*)d_in[4];
    const float* bn1_g   = (const float*)d_in[5];
    const float* bn1_b   = (const float*)d_in[6];
    const float* in_w    = (const float*)d_in[7];
    const float* in_b    = (const float*)d_in[8];
    const float* out_w   = (const float*)d_in[9];
    const float* out_b   = (const float*)d_in[10];
    const float* c1_w    = (const float*)d_in[11];
    const float* c1_b    = (const float*)d_in[12];
    float* out = (float*)d_out;

    cudaFuncSetAttribute(k_qkv,  cudaFuncAttributeMaxDynamicSharedMemorySize, 84 * 1024);
    cudaFuncSetAttribute(k_attn, cudaFuncAttributeMaxDynamicSharedMemorySize, 156 * 1024);

    k_conv0<<<dim3(96, 32), 256>>>(h, conv0_w, conv0_b);
    k_stats<<<dim3(64, 72), 256>>>(0);
    k_finalize<<<1, 64>>>(0, bn0_g, bn0_b);
    k_qkv<<<dim3(72, 32), 256, 82944>>>(in_w, in_b);
    k_attn<<<2304, 256, 154624>>>(out_w, out_b);
    k_stats<<<dim3(64, 72), 256>>>(1);
    k_finalize<<<1, 64>>>(1, bn1_g, bn1_b);
    k_mred<<<2048, 256>>>();
    k_kern<<<1, 256>>>(c1_w, c1_b);
    k_dyn<<<dim3(12, 2048), 256>>>(h, out);
}